// round 4
// baseline (speedup 1.0000x reference)
#include <cuda_runtime.h>

// Neural CDE, B=128, T=1024, D=32, H=64, W=128.
// Strategy: recurrence is independent per batch element -> persistent kernel,
// 64 CTAs x 256 threads, each CTA owns 2 batch elements and runs all 1023
// steps with only __syncthreads(). Small weights (vW0, vW1, biases) live in
// SMEM; the big vW2 (2112x128 fp32 = 1.08MB) is streamed from L2 each step,
// amortized over the 2 batches (register-blocked 2 rows x 2 batches).

namespace {

constexpr int Bn = 128;
constexpr int Tn = 1024;
constexpr int Dn = 32;
constexpr int Hn = 64;
constexpr int Wn = 128;
constexpr int Cn = Dn + 1;      // 33
constexpr int On = Hn * Cn;     // 2112
constexpr int NB = 2;           // batches per CTA
constexpr int NCTA = Bn / NB;   // 64
constexpr int NT = 256;

struct __align__(16) Smem {
  float vW0[Wn][68];     // padded from 65 (16B-aligned rows, odd float4 stride)
  float vW1[Wn][132];    // padded from 128 (stride 33 float4s -> conflict-free)
  float vb0[Wn];
  float vb1[Wn];
  float vb2[On];
  float z1[NB][Wn];
  float z2[NB][Wn];
  float v[NB][On];       // vector field values, kept across one step
  float y[NB][Hn];
  float yhat[NB][Hn];
  float s_old[NB][Hn];
  float inp[NB][68];     // [t, yhat(64), 0-pad]
  float dx[NB][36];
  float xprev[NB][36];
  float rW[Hn];
  float rb;
  float pad_[3];
};

__device__ __forceinline__ float lipswish(float x) {
  // 0.909 * x * sigmoid(x)
  float e = __expf(-x);                       // -> +inf for very negative x
  return __fdividef(0.909f * x, 1.0f + e);    // a * rcp(inf) = 0, graceful
}

__device__ __forceinline__ float fast_tanh(float x) {
  // tanh(x) = 1 - 2/(exp(2x)+1); saturates correctly at +/-1 for |x| large
  float p = __expf(2.0f * x);
  return 1.0f - __fdividef(2.0f, p + 1.0f);
}

__device__ __forceinline__ float dot4(float4 a, float4 b, float acc) {
  acc = fmaf(a.x, b.x, acc);
  acc = fmaf(a.y, b.y, acc);
  acc = fmaf(a.z, b.z, acc);
  acc = fmaf(a.w, b.w, acc);
  return acc;
}

// vf(t, y): inp must already hold [t, y, 0...] for both batches.
// Writes sm.v (tanh output) for both batches. Ends with __syncthreads().
__device__ __forceinline__ void vf_eval(Smem& sm, const float* __restrict__ vW2) {
  const int tid = threadIdx.x;
  const int nb = tid >> 7;
  const int w = tid & 127;

  // ---- layer 1: z1 = lipswish(vW0 @ inp + vb0), 256 threads = 2b x 128w ----
  {
    float a = sm.vb0[w];
    const float4* wr = reinterpret_cast<const float4*>(&sm.vW0[w][0]);
    const float4* ir = reinterpret_cast<const float4*>(&sm.inp[nb][0]);
#pragma unroll
    for (int q = 0; q < 17; ++q) a = dot4(wr[q], ir[q], a);   // 68 (pads are 0)
    sm.z1[nb][w] = lipswish(a);
  }
  __syncthreads();

  // ---- layer 2: z2 = lipswish(vW1 @ z1 + vb1) ----
  {
    float a = sm.vb1[w];
    const float4* wr = reinterpret_cast<const float4*>(&sm.vW1[w][0]);
    const float4* zr = reinterpret_cast<const float4*>(&sm.z1[nb][0]);
#pragma unroll
    for (int q = 0; q < 32; ++q) a = dot4(wr[q], zr[q], a);
    sm.z2[nb][w] = lipswish(a);
  }
  __syncthreads();

  // ---- layer 3: v = tanh(vW2 @ z2 + vb2), vW2 streamed from L2 ----
  // Register blocking: 2 output rows x 2 batches per inner pass so each
  // 128B of vW2 feeds 16 FFMAs (2 bytes/FFMA-lane -> matches L2 rate).
  {
    const float4* zb0 = reinterpret_cast<const float4*>(&sm.z2[0][0]);
    const float4* zb1 = reinterpret_cast<const float4*>(&sm.z2[1][0]);
#pragma unroll 1
    for (int j = 0; j < 4; ++j) {
      const int o0 = tid + 512 * j;
      const int o1 = o0 + 256;
      const float4* r0 = reinterpret_cast<const float4*>(vW2 + (size_t)o0 * Wn);
      const float4* r1 = reinterpret_cast<const float4*>(vW2 + (size_t)o1 * Wn);
      float a00 = 0.f, a01 = 0.f, a10 = 0.f, a11 = 0.f;
#pragma unroll
      for (int q = 0; q < 32; ++q) {
        float4 w0 = r0[q];
        float4 w1 = r1[q];
        float4 zv0 = zb0[q];   // broadcast LDS.128
        float4 zv1 = zb1[q];
        a00 = dot4(w0, zv0, a00);
        a01 = dot4(w0, zv1, a01);
        a10 = dot4(w1, zv0, a10);
        a11 = dot4(w1, zv1, a11);
      }
      const float b0v = sm.vb2[o0];
      const float b1v = sm.vb2[o1];
      sm.v[0][o0] = fast_tanh(a00 + b0v);
      sm.v[1][o0] = fast_tanh(a01 + b0v);
      sm.v[0][o1] = fast_tanh(a10 + b1v);
      sm.v[1][o1] = fast_tanh(a11 + b1v);
    }
    if (tid < On - 2048) {  // tail rows 2048..2111
      const int o = 2048 + tid;
      const float4* r0 = reinterpret_cast<const float4*>(vW2 + (size_t)o * Wn);
      float a0 = 0.f, a1 = 0.f;
#pragma unroll
      for (int q = 0; q < 32; ++q) {
        float4 w0 = r0[q];
        a0 = dot4(w0, zb0[q], a0);
        a1 = dot4(w0, zb1[q], a1);
      }
      const float bv = sm.vb2[o];
      sm.v[0][o] = fast_tanh(a0 + bv);
      sm.v[1][o] = fast_tanh(a1 + bv);
    }
  }
  __syncthreads();
}

__global__ void __launch_bounds__(NT, 1)
ncde_kernel(const float* __restrict__ ts, const float* __restrict__ ys,
            const float* __restrict__ iW0, const float* __restrict__ ib0,
            const float* __restrict__ iW1, const float* __restrict__ ib1,
            const float* __restrict__ iW2, const float* __restrict__ ib2,
            const float* __restrict__ vW0, const float* __restrict__ vb0,
            const float* __restrict__ vW1, const float* __restrict__ vb1,
            const float* __restrict__ vW2, const float* __restrict__ vb2,
            const float* __restrict__ rW, const float* __restrict__ rb,
            float* __restrict__ out) {
  extern __shared__ char smem_raw[];
  Smem& sm = *reinterpret_cast<Smem*>(smem_raw);
  const int tid = threadIdx.x;
  const int b0 = blockIdx.x * NB;

  // ---- load small weights into SMEM ----
  for (int i = tid; i < Wn * 68; i += NT) {
    int r = i / 68, c = i - r * 68;
    sm.vW0[r][c] = (c < 65) ? vW0[r * 65 + c] : 0.0f;
  }
  for (int i = tid; i < Wn * Wn; i += NT) sm.vW1[i >> 7][i & 127] = vW1[i];
  if (tid < Wn) { sm.vb0[tid] = vb0[tid]; sm.vb1[tid] = vb1[tid]; }
  for (int i = tid; i < On; i += NT) sm.vb2[i] = vb2[i];
  if (tid < Hn) sm.rW[tid] = rW[tid];
  if (tid == 0) sm.rb = rb[0];
  if (tid < NB * 3) sm.inp[tid / 3][65 + (tid % 3)] = 0.0f;  // inp pads
  // x0 = [ts[0], ys[b,0,:]]
  if (tid < NB * Cn) {
    int nb = tid / Cn, c = tid - nb * Cn;
    int b = b0 + nb;
    sm.xprev[nb][c] = (c == 0) ? ts[0] : ys[((size_t)b * Tn) * Dn + (c - 1)];
  }
  __syncthreads();

  // ---- initial MLP: y0 = iW2 @ relu(iW1 @ relu(iW0 @ x0 + ib0) + ib1) + ib2
  {
    int nb = tid >> 7, w = tid & 127;
    float a = ib0[w];
    for (int j = 0; j < Cn; ++j) a = fmaf(iW0[w * Cn + j], sm.xprev[nb][j], a);
    sm.z1[nb][w] = fmaxf(a, 0.0f);
  }
  __syncthreads();
  {
    int nb = tid >> 7, w = tid & 127;
    float a = ib1[w];
    for (int j = 0; j < Wn; ++j) a = fmaf(iW1[w * Wn + j], sm.z1[nb][j], a);
    sm.z2[nb][w] = fmaxf(a, 0.0f);
  }
  __syncthreads();
  if (tid < NB * Hn) {
    int nb = tid >> 6, h = tid & 63;
    float a = ib2[h];
    for (int j = 0; j < Wn; ++j) a = fmaf(iW2[h * Wn + j], sm.z2[nb][j], a);
    sm.y[nb][h] = a;
    sm.yhat[nb][h] = a;
    sm.inp[nb][1 + h] = a;
  } else if (tid < NB * Hn + NB) {
    sm.inp[tid - NB * Hn][0] = ts[0];
  }
  __syncthreads();

  // v0 = vf(ts[0], y0)
  vf_eval(sm, vW2);

  // ---- main scan over 1023 steps ----
  for (int t = 1; t < Tn; ++t) {
    // dx = x[t] - x[t-1]
    if (tid < NB * Cn) {
      int nb = tid / Cn, c = tid - nb * Cn;
      int b = b0 + nb;
      float x = (c == 0) ? ts[t] : ys[((size_t)b * Tn + t) * Dn + (c - 1)];
      sm.dx[nb][c] = x - sm.xprev[nb][c];
      sm.xprev[nb][c] = x;
    }
    __syncthreads();
    // s_old = einsum(v_old, dx); yhat <- 2y - yhat + s_old; build vf input
    if (tid < NB * Hn) {
      int nb = tid >> 6, h = tid & 63;
      const float* vr = &sm.v[nb][h * Cn];
      const float* dxr = &sm.dx[nb][0];
      float s = 0.0f;
#pragma unroll
      for (int c = 0; c < Cn; ++c) s = fmaf(vr[c], dxr[c], s);
      float yh = 2.0f * sm.y[nb][h] - sm.yhat[nb][h] + s;
      sm.yhat[nb][h] = yh;
      sm.s_old[nb][h] = s;
      sm.inp[nb][1 + h] = yh;
    } else if (tid < NB * Hn + NB) {
      sm.inp[tid - NB * Hn][0] = ts[t];
    }
    __syncthreads();

    vf_eval(sm, vW2);  // v <- vf(ts[t], yhat)

    // y <- y + 0.5 * (s_old + einsum(v_new, dx))
    if (tid < NB * Hn) {
      int nb = tid >> 6, h = tid & 63;
      const float* vr = &sm.v[nb][h * Cn];
      const float* dxr = &sm.dx[nb][0];
      float s = 0.0f;
#pragma unroll
      for (int c = 0; c < Cn; ++c) s = fmaf(vr[c], dxr[c], s);
      sm.y[nb][h] += 0.5f * (sm.s_old[nb][h] + s);
    }
    __syncthreads();
  }

  // ---- readout: out[b] = y[b] . rW + rb ----
  if (tid < NB) {
    float a = sm.rb;
    for (int h = 0; h < Hn; ++h) a = fmaf(sm.y[tid][h], sm.rW[h], a);
    out[b0 + tid] = a;
  }
}

}  // namespace

extern "C" void kernel_launch(void* const* d_in, const int* in_sizes, int n_in,
                              void* d_out, int out_size) {
  const float* ts  = (const float*)d_in[0];
  const float* ys  = (const float*)d_in[1];
  const float* iW0 = (const float*)d_in[2];
  const float* ib0 = (const float*)d_in[3];
  const float* iW1 = (const float*)d_in[4];
  const float* ib1 = (const float*)d_in[5];
  const float* iW2 = (const float*)d_in[6];
  const float* ib2 = (const float*)d_in[7];
  const float* vW0 = (const float*)d_in[8];
  const float* vb0 = (const float*)d_in[9];
  const float* vW1 = (const float*)d_in[10];
  const float* vb1 = (const float*)d_in[11];
  const float* vW2 = (const float*)d_in[12];
  const float* vb2 = (const float*)d_in[13];
  const float* rW  = (const float*)d_in[14];
  const float* rb  = (const float*)d_in[15];
  float* out = (float*)d_out;

  cudaFuncSetAttribute(ncde_kernel, cudaFuncAttributeMaxDynamicSharedMemorySize,
                       (int)sizeof(Smem));
  ncde_kernel<<<NCTA, NT, sizeof(Smem)>>>(ts, ys, iW0, ib0, iW1, ib1, iW2, ib2,
                                          vW0, vb0, vW1, vb1, vW2, vb2, rW, rb,
                                          out);
}

// round 5
// speedup vs baseline: 2.5942x; 2.5942x over previous
#include <cuda_runtime.h>

// Neural CDE, B=128, T=1024, D=32, H=64, W=128.
// 64 persistent CTAs x 512 threads; each CTA owns 2 batch elements for all
// 1023 sequential steps. Small weights in SMEM; vW2 (2112x128 fp32, 1.08MB)
// streamed from L2 each step with COALESCED half-warp-per-row loads +
// intra-half shuffle reduction (R3 was L1tex-wavefront-bound: 32 lines per
// warp LDG). tanh applied in a separate elementwise pass to avoid
// warp-redundant MUFU.

namespace {

constexpr int Bn = 128;
constexpr int Tn = 1024;
constexpr int Dn = 32;
constexpr int Hn = 64;
constexpr int Wn = 128;
constexpr int Cn = Dn + 1;      // 33
constexpr int On = Hn * Cn;     // 2112
constexpr int NB = 2;           // batches per CTA
constexpr int NCTA = Bn / NB;   // 64
constexpr int NT = 512;         // 16 warps
constexpr int ROWS_PER_WARP = On / (NT / 32);  // 132

struct __align__(16) Smem {
  float vW0[Wn][68];     // padded from 65; phase-free LDS.128 (4w-bank stride)
  float vW1[Wn][132];    // padded from 128
  float vb0[Wn];
  float vb1[Wn];
  float vb2[On];
  float z1[NB][Wn];
  float z2[NB][Wn];
  float vraw[On][2];     // layer-3 pre-activations (both batches)
  float v[NB][On];       // tanh(vraw + b) — vector field values
  float y[NB][Hn];       // used only for final readout staging
  float inp[NB][68];     // [t, yhat(64), 0-pad]
  float dx[NB][36];
  float rW[Hn];
  float rb;
  float pad_[3];
};

__device__ __forceinline__ float lipswish(float x) {
  float e = __expf(-x);
  return __fdividef(0.909f * x, 1.0f + e);
}

__device__ __forceinline__ float fast_tanh(float x) {
  float p = __expf(2.0f * x);
  return 1.0f - __fdividef(2.0f, p + 1.0f);
}

__device__ __forceinline__ float dot4(float4 a, float4 b, float acc) {
  acc = fmaf(a.x, b.x, acc);
  acc = fmaf(a.y, b.y, acc);
  acc = fmaf(a.z, b.z, acc);
  acc = fmaf(a.w, b.w, acc);
  return acc;
}

// vf(t, y): sm.inp must hold [t, y, 0...]. Writes sm.v. Ends with sync.
__device__ __forceinline__ void vf_eval(Smem& sm, const float* __restrict__ vW2) {
  const int tid = threadIdx.x;

  // ---- layer 1: z1 = lipswish(vW0 @ inp + vb0); 256 threads = 2b x 128w ----
  if (tid < 256) {
    const int nb = tid >> 7, w = tid & 127;
    float a = sm.vb0[w];
    const float4* wr = reinterpret_cast<const float4*>(&sm.vW0[w][0]);
    const float4* ir = reinterpret_cast<const float4*>(&sm.inp[nb][0]);
#pragma unroll
    for (int q = 0; q < 17; ++q) a = dot4(wr[q], ir[q], a);
    sm.z1[nb][w] = lipswish(a);
  }
  __syncthreads();

  // ---- layer 2: z2 = lipswish(vW1 @ z1 + vb1) ----
  if (tid < 256) {
    const int nb = tid >> 7, w = tid & 127;
    float a = sm.vb1[w];
    const float4* wr = reinterpret_cast<const float4*>(&sm.vW1[w][0]);
    const float4* zr = reinterpret_cast<const float4*>(&sm.z1[nb][0]);
#pragma unroll
    for (int q = 0; q < 32; ++q) a = dot4(wr[q], zr[q], a);
    sm.z2[nb][w] = lipswish(a);
  }
  __syncthreads();

  // ---- layer 3 phase A: vraw = vW2 @ z2 (coalesced, all 16 warps) ----
  // Half-warp per row: lanes 0-15 -> row pair member 0, lanes 16-31 -> member 1.
  // Each warp LDG.128 covers 2 rows x 256B contiguous = 4 lines (minimal).
  {
    const int wid = tid >> 5;
    const int lane = tid & 31;
    const int sub = lane >> 4;            // which row of the pair
    const int klf = (lane & 15) << 2;     // float offset within half-row

    float4 zA0 = *reinterpret_cast<const float4*>(&sm.z2[0][klf]);
    float4 zB0 = *reinterpret_cast<const float4*>(&sm.z2[0][klf + 64]);
    float4 zA1 = *reinterpret_cast<const float4*>(&sm.z2[1][klf]);
    float4 zB1 = *reinterpret_cast<const float4*>(&sm.z2[1][klf + 64]);

    const int rbase = wid * ROWS_PER_WARP;
    const float* base = vW2 + (size_t)(rbase + sub) * Wn + klf;

#pragma unroll 2
    for (int i = 0; i < ROWS_PER_WARP / 4; ++i) {   // 4 rows per body
      const float* p0 = base + (size_t)i * 512;     // rows rbase+4i+{0,1}
      const float* p1 = p0 + 256;                   // rows rbase+4i+{2,3}
      float4 wa0 = *reinterpret_cast<const float4*>(p0);
      float4 wb0 = *reinterpret_cast<const float4*>(p0 + 64);
      float4 wa1 = *reinterpret_cast<const float4*>(p1);
      float4 wb1 = *reinterpret_cast<const float4*>(p1 + 64);
      float s00 = dot4(wb0, zB0, dot4(wa0, zA0, 0.0f));  // pair0, batch0
      float s01 = dot4(wb0, zB1, dot4(wa0, zA1, 0.0f));  // pair0, batch1
      float s10 = dot4(wb1, zB0, dot4(wa1, zA0, 0.0f));  // pair1, batch0
      float s11 = dot4(wb1, zB1, dot4(wa1, zA1, 0.0f));  // pair1, batch1
#pragma unroll
      for (int m = 1; m < 16; m <<= 1) {             // reduce within 16 lanes
        s00 += __shfl_xor_sync(0xffffffffu, s00, m);
        s01 += __shfl_xor_sync(0xffffffffu, s01, m);
        s10 += __shfl_xor_sync(0xffffffffu, s10, m);
        s11 += __shfl_xor_sync(0xffffffffu, s11, m);
      }
      if ((lane & 15) == 0) {                        // lanes 0 & 16 hold sums
        const int r0 = rbase + 4 * i + sub;
        const int r1 = r0 + 2;
        *reinterpret_cast<float2*>(&sm.vraw[r0][0]) = make_float2(s00, s01);
        *reinterpret_cast<float2*>(&sm.vraw[r1][0]) = make_float2(s10, s11);
      }
    }
  }
  __syncthreads();

  // ---- layer 3 phase B: v = tanh(vraw + vb2), elementwise across lanes ----
  for (int o = tid; o < On; o += NT) {
    const float bias = sm.vb2[o];
    const float2 raw = *reinterpret_cast<const float2*>(&sm.vraw[o][0]);
    sm.v[0][o] = fast_tanh(raw.x + bias);
    sm.v[1][o] = fast_tanh(raw.y + bias);
  }
  __syncthreads();
}

__global__ void __launch_bounds__(NT, 1)
ncde_kernel(const float* __restrict__ ts, const float* __restrict__ ys,
            const float* __restrict__ iW0, const float* __restrict__ ib0,
            const float* __restrict__ iW1, const float* __restrict__ ib1,
            const float* __restrict__ iW2, const float* __restrict__ ib2,
            const float* __restrict__ vW0, const float* __restrict__ vb0,
            const float* __restrict__ vW1, const float* __restrict__ vb1,
            const float* __restrict__ vW2, const float* __restrict__ vb2,
            const float* __restrict__ rW, const float* __restrict__ rb,
            float* __restrict__ out) {
  extern __shared__ char smem_raw[];
  Smem& sm = *reinterpret_cast<Smem*>(smem_raw);
  const int tid = threadIdx.x;
  const int b0 = blockIdx.x * NB;

  // ---- load small weights into SMEM ----
  for (int i = tid; i < Wn * 68; i += NT) {
    int r = i / 68, c = i - r * 68;
    sm.vW0[r][c] = (c < 65) ? vW0[r * 65 + c] : 0.0f;
  }
  for (int i = tid; i < Wn * Wn; i += NT) sm.vW1[i >> 7][i & 127] = vW1[i];
  if (tid < Wn) { sm.vb0[tid] = vb0[tid]; sm.vb1[tid] = vb1[tid]; }
  for (int i = tid; i < On; i += NT) sm.vb2[i] = vb2[i];
  if (tid < Hn) sm.rW[tid] = rW[tid];
  if (tid == 0) sm.rb = rb[0];
  if (tid < NB * 3) sm.inp[tid / 3][65 + (tid % 3)] = 0.0f;  // inp pads

  // ---- x-prefetch registers (tid < 66 only) ----
  const int nb_p = tid / Cn;                 // batch within CTA
  const int c_p = tid - nb_p * Cn;           // channel 0..32
  const int b_p = b0 + nb_p;
  float xp = 0.0f, xn = 0.0f;
  if (tid < NB * Cn) {
    xp = (c_p == 0) ? ts[0] : ys[((size_t)b_p * Tn) * Dn + (c_p - 1)];
    xn = (c_p == 0) ? ts[1] : ys[((size_t)b_p * Tn + 1) * Dn + (c_p - 1)];
    sm.dx[nb_p][c_p] = xp;                   // stage x0 for initial MLP
    if (c_p == 0) sm.inp[nb_p][0] = xp;      // inp[.][0] = ts[0]
  }
  __syncthreads();

  // ---- initial MLP: y0 (kept in registers of threads tid < 128) ----
  if (tid < 256) {
    const int nb = tid >> 7, w = tid & 127;
    float a = ib0[w];
    for (int j = 0; j < Cn; ++j) a = fmaf(iW0[w * Cn + j], sm.dx[nb][j], a);
    sm.z1[nb][w] = fmaxf(a, 0.0f);
  }
  __syncthreads();
  if (tid < 256) {
    const int nb = tid >> 7, w = tid & 127;
    float a = ib1[w];
    for (int j = 0; j < Wn; ++j) a = fmaf(iW1[w * Wn + j], sm.z1[nb][j], a);
    sm.z2[nb][w] = fmaxf(a, 0.0f);
  }
  __syncthreads();

  // per-thread recurrence state (valid for tid < 128): batch nb_s, hidden h_s
  const int nb_s = tid >> 6;
  const int h_s = tid & 63;
  float y_r = 0.0f, yhat_r = 0.0f, s_old_r = 0.0f;
  if (tid < NB * Hn) {
    float a = ib2[h_s];
    for (int j = 0; j < Wn; ++j) a = fmaf(iW2[h_s * Wn + j], sm.z2[nb_s][j], a);
    y_r = a;
    yhat_r = a;
    sm.inp[nb_s][1 + h_s] = a;
  }
  __syncthreads();

  // v0 = vf(ts[0], y0)
  vf_eval(sm, vW2);

  // ---- main scan over 1023 steps ----
#pragma unroll 1
  for (int t = 1; t < Tn; ++t) {
    // phase 1: dx = x[t] - x[t-1]; prefetch x[t+1]; publish ts[t] to inp
    if (tid < NB * Cn) {
      sm.dx[nb_p][c_p] = xn - xp;
      xp = xn;
      if (c_p == 0) sm.inp[nb_p][0] = xp;    // = ts[t]
      const int tn = (t + 1 < Tn) ? (t + 1) : t;
      xn = (c_p == 0) ? ts[tn] : ys[((size_t)b_p * Tn + tn) * Dn + (c_p - 1)];
    }
    __syncthreads();

    // phase 2: s_old = v_old . dx ; yhat <- 2y - yhat + s_old ; build vf input
    if (tid < NB * Hn) {
      const float* vr = &sm.v[nb_s][h_s * Cn];
      const float* dxr = &sm.dx[nb_s][0];
      float s = 0.0f;
#pragma unroll
      for (int c = 0; c < Cn; ++c) s = fmaf(vr[c], dxr[c], s);
      const float yh = 2.0f * y_r - yhat_r + s;
      yhat_r = yh;
      s_old_r = s;
      sm.inp[nb_s][1 + h_s] = yh;
    }
    __syncthreads();

    vf_eval(sm, vW2);  // v <- vf(ts[t], yhat)

    // phase 4: y <- y + 0.5 * (s_old + v_new . dx)
    if (tid < NB * Hn) {
      const float* vr = &sm.v[nb_s][h_s * Cn];
      const float* dxr = &sm.dx[nb_s][0];
      float s = 0.0f;
#pragma unroll
      for (int c = 0; c < Cn; ++c) s = fmaf(vr[c], dxr[c], s);
      y_r += 0.5f * (s_old_r + s);
    }
    __syncthreads();
  }

  // ---- readout: out[b] = y[b] . rW + rb ----
  if (tid < NB * Hn) sm.y[nb_s][h_s] = y_r;
  __syncthreads();
  if (tid < NB) {
    float a = sm.rb;
    for (int h = 0; h < Hn; ++h) a = fmaf(sm.y[tid][h], sm.rW[h], a);
    out[b0 + tid] = a;
  }
}

}  // namespace

extern "C" void kernel_launch(void* const* d_in, const int* in_sizes, int n_in,
                              void* d_out, int out_size) {
  const float* ts  = (const float*)d_in[0];
  const float* ys  = (const float*)d_in[1];
  const float* iW0 = (const float*)d_in[2];
  const float* ib0 = (const float*)d_in[3];
  const float* iW1 = (const float*)d_in[4];
  const float* ib1 = (const float*)d_in[5];
  const float* iW2 = (const float*)d_in[6];
  const float* ib2 = (const float*)d_in[7];
  const float* vW0 = (const float*)d_in[8];
  const float* vb0 = (const float*)d_in[9];
  const float* vW1 = (const float*)d_in[10];
  const float* vb1 = (const float*)d_in[11];
  const float* vW2 = (const float*)d_in[12];
  const float* vb2 = (const float*)d_in[13];
  const float* rW  = (const float*)d_in[14];
  const float* rb  = (const float*)d_in[15];
  float* out = (float*)d_out;

  cudaFuncSetAttribute(ncde_kernel, cudaFuncAttributeMaxDynamicSharedMemorySize,
                       (int)sizeof(Smem));
  ncde_kernel<<<NCTA, NT, sizeof(Smem)>>>(ts, ys, iW0, ib0, iW1, ib1, iW2, ib2,
                                          vW0, vb0, vW1, vb1, vW2, vb2, rW, rb,
                                          out);
}

// round 6
// speedup vs baseline: 2.5982x; 1.0015x over previous
#include <cuda_runtime.h>

// Neural CDE, B=128, T=1024, D=32, H=64, W=128.
// 64 persistent CTAs x 512 threads; each CTA owns 2 batch elements for all
// 1023 sequential steps. Small weights in SMEM; vW2 (2112x128 fp32, 1.08MB)
// streamed from L2 each step with COALESCED half-warp-per-row loads +
// intra-half shuffle reduction (R3 was L1tex-wavefront-bound: 32 lines per
// warp LDG). tanh applied in a separate elementwise pass to avoid
// warp-redundant MUFU.

namespace {

constexpr int Bn = 128;
constexpr int Tn = 1024;
constexpr int Dn = 32;
constexpr int Hn = 64;
constexpr int Wn = 128;
constexpr int Cn = Dn + 1;      // 33
constexpr int On = Hn * Cn;     // 2112
constexpr int NB = 2;           // batches per CTA
constexpr int NCTA = Bn / NB;   // 64
constexpr int NT = 512;         // 16 warps
constexpr int ROWS_PER_WARP = On / (NT / 32);  // 132

struct __align__(16) Smem {
  float vW0[Wn][68];     // padded from 65; phase-free LDS.128 (4w-bank stride)
  float vW1[Wn][132];    // padded from 128
  float vb0[Wn];
  float vb1[Wn];
  float vb2[On];
  float z1[NB][Wn];
  float z2[NB][Wn];
  float vraw[On][2];     // layer-3 pre-activations (both batches)
  float v[NB][On];       // tanh(vraw + b) — vector field values
  float y[NB][Hn];       // used only for final readout staging
  float inp[NB][68];     // [t, yhat(64), 0-pad]
  float dx[NB][36];
  float rW[Hn];
  float rb;
  float pad_[3];
};

__device__ __forceinline__ float lipswish(float x) {
  float e = __expf(-x);
  return __fdividef(0.909f * x, 1.0f + e);
}

__device__ __forceinline__ float fast_tanh(float x) {
  float p = __expf(2.0f * x);
  return 1.0f - __fdividef(2.0f, p + 1.0f);
}

__device__ __forceinline__ float dot4(float4 a, float4 b, float acc) {
  acc = fmaf(a.x, b.x, acc);
  acc = fmaf(a.y, b.y, acc);
  acc = fmaf(a.z, b.z, acc);
  acc = fmaf(a.w, b.w, acc);
  return acc;
}

// vf(t, y): sm.inp must hold [t, y, 0...]. Writes sm.v. Ends with sync.
__device__ __forceinline__ void vf_eval(Smem& sm, const float* __restrict__ vW2) {
  const int tid = threadIdx.x;

  // ---- layer 1: z1 = lipswish(vW0 @ inp + vb0); 256 threads = 2b x 128w ----
  if (tid < 256) {
    const int nb = tid >> 7, w = tid & 127;
    float a = sm.vb0[w];
    const float4* wr = reinterpret_cast<const float4*>(&sm.vW0[w][0]);
    const float4* ir = reinterpret_cast<const float4*>(&sm.inp[nb][0]);
#pragma unroll
    for (int q = 0; q < 17; ++q) a = dot4(wr[q], ir[q], a);
    sm.z1[nb][w] = lipswish(a);
  }
  __syncthreads();

  // ---- layer 2: z2 = lipswish(vW1 @ z1 + vb1) ----
  if (tid < 256) {
    const int nb = tid >> 7, w = tid & 127;
    float a = sm.vb1[w];
    const float4* wr = reinterpret_cast<const float4*>(&sm.vW1[w][0]);
    const float4* zr = reinterpret_cast<const float4*>(&sm.z1[nb][0]);
#pragma unroll
    for (int q = 0; q < 32; ++q) a = dot4(wr[q], zr[q], a);
    sm.z2[nb][w] = lipswish(a);
  }
  __syncthreads();

  // ---- layer 3 phase A: vraw = vW2 @ z2 (coalesced, all 16 warps) ----
  // Half-warp per row: lanes 0-15 -> row pair member 0, lanes 16-31 -> member 1.
  // Each warp LDG.128 covers 2 rows x 256B contiguous = 4 lines (minimal).
  {
    const int wid = tid >> 5;
    const int lane = tid & 31;
    const int sub = lane >> 4;            // which row of the pair
    const int klf = (lane & 15) << 2;     // float offset within half-row

    float4 zA0 = *reinterpret_cast<const float4*>(&sm.z2[0][klf]);
    float4 zB0 = *reinterpret_cast<const float4*>(&sm.z2[0][klf + 64]);
    float4 zA1 = *reinterpret_cast<const float4*>(&sm.z2[1][klf]);
    float4 zB1 = *reinterpret_cast<const float4*>(&sm.z2[1][klf + 64]);

    const int rbase = wid * ROWS_PER_WARP;
    const float* base = vW2 + (size_t)(rbase + sub) * Wn + klf;

#pragma unroll 2
    for (int i = 0; i < ROWS_PER_WARP / 4; ++i) {   // 4 rows per body
      const float* p0 = base + (size_t)i * 512;     // rows rbase+4i+{0,1}
      const float* p1 = p0 + 256;                   // rows rbase+4i+{2,3}
      float4 wa0 = *reinterpret_cast<const float4*>(p0);
      float4 wb0 = *reinterpret_cast<const float4*>(p0 + 64);
      float4 wa1 = *reinterpret_cast<const float4*>(p1);
      float4 wb1 = *reinterpret_cast<const float4*>(p1 + 64);
      float s00 = dot4(wb0, zB0, dot4(wa0, zA0, 0.0f));  // pair0, batch0
      float s01 = dot4(wb0, zB1, dot4(wa0, zA1, 0.0f));  // pair0, batch1
      float s10 = dot4(wb1, zB0, dot4(wa1, zA0, 0.0f));  // pair1, batch0
      float s11 = dot4(wb1, zB1, dot4(wa1, zA1, 0.0f));  // pair1, batch1
#pragma unroll
      for (int m = 1; m < 16; m <<= 1) {             // reduce within 16 lanes
        s00 += __shfl_xor_sync(0xffffffffu, s00, m);
        s01 += __shfl_xor_sync(0xffffffffu, s01, m);
        s10 += __shfl_xor_sync(0xffffffffu, s10, m);
        s11 += __shfl_xor_sync(0xffffffffu, s11, m);
      }
      if ((lane & 15) == 0) {                        // lanes 0 & 16 hold sums
        const int r0 = rbase + 4 * i + sub;
        const int r1 = r0 + 2;
        *reinterpret_cast<float2*>(&sm.vraw[r0][0]) = make_float2(s00, s01);
        *reinterpret_cast<float2*>(&sm.vraw[r1][0]) = make_float2(s10, s11);
      }
    }
  }
  __syncthreads();

  // ---- layer 3 phase B: v = tanh(vraw + vb2), elementwise across lanes ----
  for (int o = tid; o < On; o += NT) {
    const float bias = sm.vb2[o];
    const float2 raw = *reinterpret_cast<const float2*>(&sm.vraw[o][0]);
    sm.v[0][o] = fast_tanh(raw.x + bias);
    sm.v[1][o] = fast_tanh(raw.y + bias);
  }
  __syncthreads();
}

__global__ void __launch_bounds__(NT, 1)
ncde_kernel(const float* __restrict__ ts, const float* __restrict__ ys,
            const float* __restrict__ iW0, const float* __restrict__ ib0,
            const float* __restrict__ iW1, const float* __restrict__ ib1,
            const float* __restrict__ iW2, const float* __restrict__ ib2,
            const float* __restrict__ vW0, const float* __restrict__ vb0,
            const float* __restrict__ vW1, const float* __restrict__ vb1,
            const float* __restrict__ vW2, const float* __restrict__ vb2,
            const float* __restrict__ rW, const float* __restrict__ rb,
            float* __restrict__ out) {
  extern __shared__ char smem_raw[];
  Smem& sm = *reinterpret_cast<Smem*>(smem_raw);
  const int tid = threadIdx.x;
  const int b0 = blockIdx.x * NB;

  // ---- load small weights into SMEM ----
  for (int i = tid; i < Wn * 68; i += NT) {
    int r = i / 68, c = i - r * 68;
    sm.vW0[r][c] = (c < 65) ? vW0[r * 65 + c] : 0.0f;
  }
  for (int i = tid; i < Wn * Wn; i += NT) sm.vW1[i >> 7][i & 127] = vW1[i];
  if (tid < Wn) { sm.vb0[tid] = vb0[tid]; sm.vb1[tid] = vb1[tid]; }
  for (int i = tid; i < On; i += NT) sm.vb2[i] = vb2[i];
  if (tid < Hn) sm.rW[tid] = rW[tid];
  if (tid == 0) sm.rb = rb[0];
  if (tid < NB * 3) sm.inp[tid / 3][65 + (tid % 3)] = 0.0f;  // inp pads

  // ---- x-prefetch registers (tid < 66 only) ----
  const int nb_p = tid / Cn;                 // batch within CTA
  const int c_p = tid - nb_p * Cn;           // channel 0..32
  const int b_p = b0 + nb_p;
  float xp = 0.0f, xn = 0.0f;
  if (tid < NB * Cn) {
    xp = (c_p == 0) ? ts[0] : ys[((size_t)b_p * Tn) * Dn + (c_p - 1)];
    xn = (c_p == 0) ? ts[1] : ys[((size_t)b_p * Tn + 1) * Dn + (c_p - 1)];
    sm.dx[nb_p][c_p] = xp;                   // stage x0 for initial MLP
    if (c_p == 0) sm.inp[nb_p][0] = xp;      // inp[.][0] = ts[0]
  }
  __syncthreads();

  // ---- initial MLP: y0 (kept in registers of threads tid < 128) ----
  if (tid < 256) {
    const int nb = tid >> 7, w = tid & 127;
    float a = ib0[w];
    for (int j = 0; j < Cn; ++j) a = fmaf(iW0[w * Cn + j], sm.dx[nb][j], a);
    sm.z1[nb][w] = fmaxf(a, 0.0f);
  }
  __syncthreads();
  if (tid < 256) {
    const int nb = tid >> 7, w = tid & 127;
    float a = ib1[w];
    for (int j = 0; j < Wn; ++j) a = fmaf(iW1[w * Wn + j], sm.z1[nb][j], a);
    sm.z2[nb][w] = fmaxf(a, 0.0f);
  }
  __syncthreads();

  // per-thread recurrence state (valid for tid < 128): batch nb_s, hidden h_s
  const int nb_s = tid >> 6;
  const int h_s = tid & 63;
  float y_r = 0.0f, yhat_r = 0.0f, s_old_r = 0.0f;
  if (tid < NB * Hn) {
    float a = ib2[h_s];
    for (int j = 0; j < Wn; ++j) a = fmaf(iW2[h_s * Wn + j], sm.z2[nb_s][j], a);
    y_r = a;
    yhat_r = a;
    sm.inp[nb_s][1 + h_s] = a;
  }
  __syncthreads();

  // v0 = vf(ts[0], y0)
  vf_eval(sm, vW2);

  // ---- main scan over 1023 steps ----
#pragma unroll 1
  for (int t = 1; t < Tn; ++t) {
    // phase 1: dx = x[t] - x[t-1]; prefetch x[t+1]; publish ts[t] to inp
    if (tid < NB * Cn) {
      sm.dx[nb_p][c_p] = xn - xp;
      xp = xn;
      if (c_p == 0) sm.inp[nb_p][0] = xp;    // = ts[t]
      const int tn = (t + 1 < Tn) ? (t + 1) : t;
      xn = (c_p == 0) ? ts[tn] : ys[((size_t)b_p * Tn + tn) * Dn + (c_p - 1)];
    }
    __syncthreads();

    // phase 2: s_old = v_old . dx ; yhat <- 2y - yhat + s_old ; build vf input
    if (tid < NB * Hn) {
      const float* vr = &sm.v[nb_s][h_s * Cn];
      const float* dxr = &sm.dx[nb_s][0];
      float s = 0.0f;
#pragma unroll
      for (int c = 0; c < Cn; ++c) s = fmaf(vr[c], dxr[c], s);
      const float yh = 2.0f * y_r - yhat_r + s;
      yhat_r = yh;
      s_old_r = s;
      sm.inp[nb_s][1 + h_s] = yh;
    }
    __syncthreads();

    vf_eval(sm, vW2);  // v <- vf(ts[t], yhat)

    // phase 4: y <- y + 0.5 * (s_old + v_new . dx)
    if (tid < NB * Hn) {
      const float* vr = &sm.v[nb_s][h_s * Cn];
      const float* dxr = &sm.dx[nb_s][0];
      float s = 0.0f;
#pragma unroll
      for (int c = 0; c < Cn; ++c) s = fmaf(vr[c], dxr[c], s);
      y_r += 0.5f * (s_old_r + s);
    }
    __syncthreads();
  }

  // ---- readout: out[b] = y[b] . rW + rb ----
  if (tid < NB * Hn) sm.y[nb_s][h_s] = y_r;
  __syncthreads();
  if (tid < NB) {
    float a = sm.rb;
    for (int h = 0; h < Hn; ++h) a = fmaf(sm.y[tid][h], sm.rW[h], a);
    out[b0 + tid] = a;
  }
}

}  // namespace

extern "C" void kernel_launch(void* const* d_in, const int* in_sizes, int n_in,
                              void* d_out, int out_size) {
  const float* ts  = (const float*)d_in[0];
  const float* ys  = (const float*)d_in[1];
  const float* iW0 = (const float*)d_in[2];
  const float* ib0 = (const float*)d_in[3];
  const float* iW1 = (const float*)d_in[4];
  const float* ib1 = (const float*)d_in[5];
  const float* iW2 = (const float*)d_in[6];
  const float* ib2 = (const float*)d_in[7];
  const float* vW0 = (const float*)d_in[8];
  const float* vb0 = (const float*)d_in[9];
  const float* vW1 = (const float*)d_in[10];
  const float* vb1 = (const float*)d_in[11];
  const float* vW2 = (const float*)d_in[12];
  const float* vb2 = (const float*)d_in[13];
  const float* rW  = (const float*)d_in[14];
  const float* rb  = (const float*)d_in[15];
  float* out = (float*)d_out;

  cudaFuncSetAttribute(ncde_kernel, cudaFuncAttributeMaxDynamicSharedMemorySize,
                       (int)sizeof(Smem));
  ncde_kernel<<<NCTA, NT, sizeof(Smem)>>>(ts, ys, iW0, ib0, iW1, ib1, iW2, ib2,
                                          vW0, vb0, vW1, vb1, vW2, vb2, rW, rb,
                                          out);
}